// round 6
// baseline (speedup 1.0000x reference)
#include <cuda_runtime.h>
#include <cstdint>
#include <cstddef>

#define B_ 256
#define L_ 512
#define D_ 768
#define C_ 19
#define CP 20
#define BL (B_*L_)

// Emission scratch, padded to 20 floats/row
__device__ float g_emis[(size_t)BL * CP];
// Score history: rows 0..512 per batch (row 0 = init, row t+1 = s after step t)
__device__ float g_hist[(size_t)B_ * (L_ + 1) * CP];

__device__ __forceinline__ unsigned long long pack2(float x){
    unsigned long long r;
    asm("mov.b64 %0, {%1, %1};" : "=l"(r) : "f"(x));
    return r;
}
__device__ __forceinline__ unsigned long long fma2(unsigned long long a,
                                                   unsigned long long b,
                                                   unsigned long long c){
    unsigned long long d;
    asm("fma.rn.f32x2 %0, %1, %2, %3;" : "=l"(d) : "l"(a), "l"(b), "l"(c));
    return d;
}

#define SMEM_A (D_ * 10 * 8)   // 61440 bytes: w2[d][p] packed class pairs

// ---------------------------------------------------------------------------
// Kernel A: emissions. 512 blocks x 128 threads, 2 rows/thread -> 3 blocks/SM
// (12 warps, all SMSPs) for latency hiding; regs stay low. LDS.128 weight
// loads (2 class-pairs per load); packed f32x2 FMA.
// ---------------------------------------------------------------------------
__global__ void __launch_bounds__(128) emis_kernel(const float* __restrict__ feats,
                                                   const float* __restrict__ W,
                                                   const float* __restrict__ bias){
    extern __shared__ unsigned long long w2[];   // [768*10]
    int tid = threadIdx.x;
    for (int i = tid; i < D_ * 10; i += 128){
        int d = i / 10, p = i % 10;
        float lo = W[(2*p) * D_ + d];
        float hi = (2*p + 1 < C_) ? W[(2*p + 1) * D_ + d] : 0.f;
        float2 t = make_float2(lo, hi);
        w2[i] = *reinterpret_cast<unsigned long long*>(&t);
    }
    __syncthreads();

    unsigned long long accA[10], accB[10];
#pragma unroll
    for (int p = 0; p < 10; p++){
        float lo = bias[2*p];
        float hi = (2*p + 1 < C_) ? bias[2*p + 1] : 0.f;
        float2 t = make_float2(lo, hi);
        accA[p] = *reinterpret_cast<unsigned long long*>(&t);
        accB[p] = accA[p];
    }

    size_t rowA = (size_t)blockIdx.x * 256 + tid;
    size_t rowB = rowA + 128;
    const float4* fA = reinterpret_cast<const float4*>(feats + rowA * D_);
    const float4* fB = reinterpret_cast<const float4*>(feats + rowB * D_);

    for (int q = 0; q < D_ / 4; q++){
        float4 a = fA[q], b = fB[q];
#pragma unroll
        for (int j = 0; j < 4; j++){
            unsigned long long pa = pack2((&a.x)[j]);
            unsigned long long pb = pack2((&b.x)[j]);
            int d = q * 4 + j;
#pragma unroll
            for (int pp = 0; pp < 5; pp++){
                ulonglong2 wv = *reinterpret_cast<const ulonglong2*>(&w2[d * 10 + pp * 2]);
                accA[2*pp]   = fma2(pa, wv.x, accA[2*pp]);
                accA[2*pp+1] = fma2(pa, wv.y, accA[2*pp+1]);
                accB[2*pp]   = fma2(pb, wv.x, accB[2*pp]);
                accB[2*pp+1] = fma2(pb, wv.y, accB[2*pp+1]);
            }
        }
    }

    unsigned long long* oA = reinterpret_cast<unsigned long long*>(g_emis + rowA * CP);
    unsigned long long* oB = reinterpret_cast<unsigned long long*>(g_emis + rowB * CP);
#pragma unroll
    for (int p = 0; p < 10; p++){ oA[p] = accA[p]; oB[p] = accB[p]; }
}

// ---------------------------------------------------------------------------
// Kernel B1: Viterbi forward. 64 blocks x 128 threads: 4 warps/block = one
// chain per SMSP (fixes the all-chains-on-SMSP0 placement of 32-thread
// blocks). SHFL gather, fma-form mask blend (bit-exact for m in {0,1}),
// history streamed to gmem for the bp kernel.
// ---------------------------------------------------------------------------
__global__ void __launch_bounds__(128) fwd_kernel(const float* __restrict__ masks,
                                                  const float* __restrict__ trans){
    __shared__ float m_sh[4][L_];
    int w = threadIdx.x >> 5, lane = threadIdx.x & 31;
    int b = blockIdx.x * 4 + w;
    bool active = lane < C_;
    int c = active ? lane : 0;

    float Trow[C_];
#pragma unroll
    for (int j = 0; j < C_; j++) Trow[j] = trans[c * C_ + j];

    const float* eb = g_emis + (size_t)b * L_ * CP;
    const float* mb = masks + (size_t)b * L_;
    float* ghb = g_hist + (size_t)b * (L_ + 1) * CP;

    for (int i = lane; i < L_; i += 32) m_sh[w][i] = mb[i];
    __syncwarp();

    float s = (lane == C_ - 2) ? 0.f : -10000.f;   // start_idx = C-2
    if (active) ghb[lane] = s;

    int ld_lane = active ? lane : 0;
    float e0 = eb[0 * CP + ld_lane];
    float e1 = eb[1 * CP + ld_lane];
    float e2 = eb[2 * CP + ld_lane];
    float e3 = eb[3 * CP + ld_lane];

#define VSTEP(T, EREG)                                                         \
    {                                                                          \
        float m = m_sh[w][T];                                                  \
        float om = 1.0f - m;                                                   \
        float inner = fmaf((EREG), m, s * om);   /* off critical path */       \
        float v[C_];                                                           \
        _Pragma("unroll")                                                      \
        for (int j = 0; j < C_; j++)                                           \
            v[j] = __shfl_sync(0xffffffffu, s, j) + Trow[j];                   \
        _Pragma("unroll")                                                      \
        for (int stp = 1; stp < C_; stp <<= 1){                                \
            _Pragma("unroll")                                                  \
            for (int j = 0; j + stp < C_; j += (stp << 1))                     \
                v[j] = fmaxf(v[j], v[j + stp]);                                \
        }                                                                      \
        s = fmaf(v[0], m, inner);                                              \
        if (active) ghb[((T) + 1) * CP + lane] = s;                            \
    }

    for (int t = 0; t < L_; t += 4){
        VSTEP(t, e0);     e0 = (t + 4 < L_) ? eb[(t + 4) * CP + ld_lane] : 0.f;
        VSTEP(t + 1, e1); e1 = (t + 5 < L_) ? eb[(t + 5) * CP + ld_lane] : 0.f;
        VSTEP(t + 2, e2); e2 = (t + 6 < L_) ? eb[(t + 6) * CP + ld_lane] : 0.f;
        VSTEP(t + 3, e3); e3 = (t + 7 < L_) ? eb[(t + 7) * CP + ld_lane] : 0.f;
    }
#undef VSTEP
}

// ---------------------------------------------------------------------------
// Kernel B2: backpointers + backtrace. One block per batch, one thread per
// timestep recomputes all 19 backpointers from the score history; thread 0
// backtraces from shared; coalesced tag writeback.
// ---------------------------------------------------------------------------
__global__ void __launch_bounds__(512) bp_kernel(const float* __restrict__ masks,
                                                 const float* __restrict__ trans,
                                                 float* __restrict__ out){
    __shared__ float T_sh[C_][CP];
    __shared__ float m2[L_];
    __shared__ signed char bp_sh[L_][CP];   // col 19 reused for tags
    int tid = threadIdx.x;
    int b = blockIdx.x;

    for (int i = tid; i < C_ * CP; i += 512){
        int cc = i / CP, j = i % CP;
        T_sh[cc][j] = (j < C_) ? trans[cc * C_ + j] : 0.f;
    }
    if (tid < L_) m2[tid] = masks[(size_t)b * L_ + tid];
    __syncthreads();

    {
        int t = tid;   // 0..511
        const float* h = g_hist + ((size_t)b * (L_ + 1) + t) * CP;
        float4 h0 = *reinterpret_cast<const float4*>(h + 0);
        float4 h1 = *reinterpret_cast<const float4*>(h + 4);
        float4 h2 = *reinterpret_cast<const float4*>(h + 8);
        float4 h3 = *reinterpret_cast<const float4*>(h + 12);
        float4 h4 = *reinterpret_cast<const float4*>(h + 16);
        float hv[C_];
        hv[0]=h0.x; hv[1]=h0.y; hv[2]=h0.z; hv[3]=h0.w;
        hv[4]=h1.x; hv[5]=h1.y; hv[6]=h1.z; hv[7]=h1.w;
        hv[8]=h2.x; hv[9]=h2.y; hv[10]=h2.z; hv[11]=h2.w;
        hv[12]=h3.x; hv[13]=h3.y; hv[14]=h3.z; hv[15]=h3.w;
        hv[16]=h4.x; hv[17]=h4.y; hv[18]=h4.z;

#pragma unroll
        for (int cc = 0; cc < C_; cc++){
            const float* tr = &T_sh[cc][0];
            float best = hv[0] + tr[0];
            int idx = 0;
#pragma unroll
            for (int j = 1; j < C_; j++){
                float val = hv[j] + tr[j];
                bool gt = val > best;          // strict > : leftmost wins ties
                best = gt ? val : best;
                idx  = gt ? j : idx;
            }
            bp_sh[t][cc] = (signed char)idx;
        }
    }

    // final score + start tag (warp 0)
    float fv = -3.4e38f; int fi = 999;
    if (tid < 32){
        int lane = tid;
        bool active = lane < C_;
        if (active)
            fv = g_hist[((size_t)b * (L_ + 1) + L_) * CP + lane]
               + trans[(C_ - 1) * C_ + lane];
        if (active) fi = lane;
#pragma unroll
        for (int off = 16; off > 0; off >>= 1){
            float ov = __shfl_down_sync(0xffffffffu, fv, off);
            int oi = __shfl_down_sync(0xffffffffu, fi, off);
            if (ov > fv || (ov == fv && oi < fi)){ fv = ov; fi = oi; }
        }
    }
    __syncthreads();

    if (tid == 0){
        out[b] = fv;
        int cur = fi;
        for (int t = L_ - 1; t >= 0; t--){
            bool valid = m2[t] > 0.f;
            bp_sh[t][C_] = valid ? (signed char)cur : (signed char)(-1);
            if (valid) cur = bp_sh[t][cur];
        }
    }
    __syncthreads();

    float* po = out + B_ + (size_t)b * L_;
    po[tid] = (float)bp_sh[tid][C_];
}

// ---------------------------------------------------------------------------
extern "C" void kernel_launch(void* const* d_in, const int* in_sizes, int n_in,
                              void* d_out, int out_size){
    const float* feats = (const float*)d_in[0];
    const float* masks = (const float*)d_in[1];
    const float* W     = (const float*)d_in[2];
    const float* bias  = (const float*)d_in[3];
    const float* trans = (const float*)d_in[4];
    float* out = (float*)d_out;

    cudaFuncSetAttribute(emis_kernel, cudaFuncAttributeMaxDynamicSharedMemorySize, SMEM_A);
    emis_kernel<<<512, 128, SMEM_A>>>(feats, W, bias);
    fwd_kernel<<<B_ / 4, 128>>>(masks, trans);
    bp_kernel<<<B_, 512>>>(masks, trans, out);
}

// round 7
// speedup vs baseline: 1.0721x; 1.0721x over previous
#include <cuda_runtime.h>
#include <cstdint>
#include <cstddef>

#define B_ 256
#define L_ 512
#define D_ 768
#define C_ 19
#define CP 20
#define BL (B_*L_)

// Emission scratch, padded to 20 floats/row
__device__ float g_emis[(size_t)BL * CP];
// Score history: rows 0..512 per batch (row 0 = init, row t+1 = s after step t)
__device__ float g_hist[(size_t)B_ * (L_ + 1) * CP];

__device__ __forceinline__ unsigned long long pack2(float x){
    unsigned long long r;
    asm("mov.b64 %0, {%1, %1};" : "=l"(r) : "f"(x));
    return r;
}
__device__ __forceinline__ unsigned long long fma2(unsigned long long a,
                                                   unsigned long long b,
                                                   unsigned long long c){
    unsigned long long d;
    asm("fma.rn.f32x2 %0, %1, %2, %3;" : "=l"(d) : "l"(a), "l"(b), "l"(c));
    return d;
}

#define SMEM_A (D_ * 10 * 8)   // 61440 bytes: w2[d][p] packed class pairs

// ---------------------------------------------------------------------------
// Kernel A: emissions. 256 blocks x 256 threads, 2 rows/thread, depth-4
// register prefetch ring (8 LDG.128 in flight/thread), launch_bounds(256,2)
// -> 2 blocks/SM = 16 warps, ~64KB in flight per SM (kernel is
// in-flight-bytes limited: R5 measured 2.47TB/s with ~16KB in flight).
// LDS.128 weight loads, packed f32x2 FMA.
// ---------------------------------------------------------------------------
__global__ void __launch_bounds__(256, 2) emis_kernel(const float* __restrict__ feats,
                                                      const float* __restrict__ W,
                                                      const float* __restrict__ bias){
    extern __shared__ unsigned long long w2[];   // [768*10]
    int tid = threadIdx.x;
    for (int i = tid; i < D_ * 10; i += 256){
        int d = i / 10, p = i % 10;
        float lo = W[(2*p) * D_ + d];
        float hi = (2*p + 1 < C_) ? W[(2*p + 1) * D_ + d] : 0.f;
        float2 t = make_float2(lo, hi);
        w2[i] = *reinterpret_cast<unsigned long long*>(&t);
    }
    __syncthreads();

    unsigned long long accA[10], accB[10];
#pragma unroll
    for (int p = 0; p < 10; p++){
        float lo = bias[2*p];
        float hi = (2*p + 1 < C_) ? bias[2*p + 1] : 0.f;
        float2 t = make_float2(lo, hi);
        accA[p] = *reinterpret_cast<unsigned long long*>(&t);
        accB[p] = accA[p];
    }

    size_t rowA = (size_t)blockIdx.x * 512 + tid;
    size_t rowB = rowA + 256;
    const float4* fA = reinterpret_cast<const float4*>(feats + rowA * D_);
    const float4* fB = reinterpret_cast<const float4*>(feats + rowB * D_);

    // depth-4 prefetch ring, constant slot indices (fully unrolled x4)
    float4 a0 = fA[0], a1 = fA[1], a2 = fA[2], a3 = fA[3];
    float4 b0 = fB[0], b1 = fB[1], b2 = fB[2], b3 = fB[3];

    const int NQ = D_ / 4;   // 192

#define EMIT4(AV, BV, QD)                                                      \
    {                                                                          \
        _Pragma("unroll")                                                      \
        for (int j = 0; j < 4; j++){                                           \
            unsigned long long pa = pack2((&(AV).x)[j]);                       \
            unsigned long long pb = pack2((&(BV).x)[j]);                       \
            int d = (QD) * 4 + j;                                              \
            _Pragma("unroll")                                                  \
            for (int pp = 0; pp < 5; pp++){                                    \
                ulonglong2 wv =                                                \
                    *reinterpret_cast<const ulonglong2*>(&w2[d * 10 + pp * 2]);\
                accA[2*pp]   = fma2(pa, wv.x, accA[2*pp]);                     \
                accA[2*pp+1] = fma2(pa, wv.y, accA[2*pp+1]);                   \
                accB[2*pp]   = fma2(pb, wv.x, accB[2*pp]);                     \
                accB[2*pp+1] = fma2(pb, wv.y, accB[2*pp+1]);                   \
            }                                                                  \
        }                                                                      \
    }

    for (int q0 = 0; q0 < NQ; q0 += 4){
        float4 ca0 = a0, ca1 = a1, ca2 = a2, ca3 = a3;
        float4 cb0 = b0, cb1 = b1, cb2 = b2, cb3 = b3;
        if (q0 + 4 < NQ){
            a0 = fA[q0 + 4]; a1 = fA[q0 + 5]; a2 = fA[q0 + 6]; a3 = fA[q0 + 7];
            b0 = fB[q0 + 4]; b1 = fB[q0 + 5]; b2 = fB[q0 + 6]; b3 = fB[q0 + 7];
        }
        EMIT4(ca0, cb0, q0);
        EMIT4(ca1, cb1, q0 + 1);
        EMIT4(ca2, cb2, q0 + 2);
        EMIT4(ca3, cb3, q0 + 3);
    }
#undef EMIT4

    unsigned long long* oA = reinterpret_cast<unsigned long long*>(g_emis + rowA * CP);
    unsigned long long* oB = reinterpret_cast<unsigned long long*>(g_emis + rowB * CP);
#pragma unroll
    for (int p = 0; p < 10; p++){ oA[p] = accA[p]; oB[p] = accB[p]; }
}

// ---------------------------------------------------------------------------
// Kernel B1: Viterbi forward (R5 config — known 87us). 256 blocks x 32 thr,
// one warp per batch. SHFL gather, fma-form mask blend (bit-exact for
// m in {0,1}), history streamed to gmem for the bp kernel.
// ---------------------------------------------------------------------------
__global__ void __launch_bounds__(32) fwd_kernel(const float* __restrict__ masks,
                                                 const float* __restrict__ trans){
    __shared__ float m_sh[L_];
    int lane = threadIdx.x & 31;
    int b = blockIdx.x;
    bool active = lane < C_;
    int c = active ? lane : 0;

    float Trow[C_];
#pragma unroll
    for (int j = 0; j < C_; j++) Trow[j] = trans[c * C_ + j];

    const float* eb = g_emis + (size_t)b * L_ * CP;
    const float* mb = masks + (size_t)b * L_;
    float* ghb = g_hist + (size_t)b * (L_ + 1) * CP;

    for (int i = lane; i < L_; i += 32) m_sh[i] = mb[i];
    __syncwarp();

    float s = (lane == C_ - 2) ? 0.f : -10000.f;   // start_idx = C-2
    if (active) ghb[lane] = s;

    int ld_lane = active ? lane : 0;
    float e0 = eb[0 * CP + ld_lane];
    float e1 = eb[1 * CP + ld_lane];
    float e2 = eb[2 * CP + ld_lane];
    float e3 = eb[3 * CP + ld_lane];

#define VSTEP(T, EREG)                                                         \
    {                                                                          \
        float m = m_sh[T];                                                     \
        float om = 1.0f - m;                                                   \
        float inner = fmaf((EREG), m, s * om);   /* off critical path */       \
        float v[C_];                                                           \
        _Pragma("unroll")                                                      \
        for (int j = 0; j < C_; j++)                                           \
            v[j] = __shfl_sync(0xffffffffu, s, j) + Trow[j];                   \
        _Pragma("unroll")                                                      \
        for (int stp = 1; stp < C_; stp <<= 1){                                \
            _Pragma("unroll")                                                  \
            for (int j = 0; j + stp < C_; j += (stp << 1))                     \
                v[j] = fmaxf(v[j], v[j + stp]);                                \
        }                                                                      \
        s = fmaf(v[0], m, inner);                                              \
        if (active) ghb[((T) + 1) * CP + lane] = s;                            \
    }

    for (int t = 0; t < L_; t += 4){
        VSTEP(t, e0);     e0 = (t + 4 < L_) ? eb[(t + 4) * CP + ld_lane] : 0.f;
        VSTEP(t + 1, e1); e1 = (t + 5 < L_) ? eb[(t + 5) * CP + ld_lane] : 0.f;
        VSTEP(t + 2, e2); e2 = (t + 6 < L_) ? eb[(t + 6) * CP + ld_lane] : 0.f;
        VSTEP(t + 3, e3); e3 = (t + 7 < L_) ? eb[(t + 7) * CP + ld_lane] : 0.f;
    }
#undef VSTEP
}

// ---------------------------------------------------------------------------
// Kernel B2: backpointers + backtrace. One block per batch, one thread per
// timestep recomputes all 19 backpointers from the score history; thread 0
// backtraces from shared; coalesced tag writeback.
// ---------------------------------------------------------------------------
__global__ void __launch_bounds__(512) bp_kernel(const float* __restrict__ masks,
                                                 const float* __restrict__ trans,
                                                 float* __restrict__ out){
    __shared__ float T_sh[C_][CP];
    __shared__ float m2[L_];
    __shared__ signed char bp_sh[L_][CP];   // col 19 reused for tags
    int tid = threadIdx.x;
    int b = blockIdx.x;

    for (int i = tid; i < C_ * CP; i += 512){
        int cc = i / CP, j = i % CP;
        T_sh[cc][j] = (j < C_) ? trans[cc * C_ + j] : 0.f;
    }
    if (tid < L_) m2[tid] = masks[(size_t)b * L_ + tid];
    __syncthreads();

    {
        int t = tid;   // 0..511
        const float* h = g_hist + ((size_t)b * (L_ + 1) + t) * CP;
        float4 h0 = *reinterpret_cast<const float4*>(h + 0);
        float4 h1 = *reinterpret_cast<const float4*>(h + 4);
        float4 h2 = *reinterpret_cast<const float4*>(h + 8);
        float4 h3 = *reinterpret_cast<const float4*>(h + 12);
        float4 h4 = *reinterpret_cast<const float4*>(h + 16);
        float hv[C_];
        hv[0]=h0.x; hv[1]=h0.y; hv[2]=h0.z; hv[3]=h0.w;
        hv[4]=h1.x; hv[5]=h1.y; hv[6]=h1.z; hv[7]=h1.w;
        hv[8]=h2.x; hv[9]=h2.y; hv[10]=h2.z; hv[11]=h2.w;
        hv[12]=h3.x; hv[13]=h3.y; hv[14]=h3.z; hv[15]=h3.w;
        hv[16]=h4.x; hv[17]=h4.y; hv[18]=h4.z;

#pragma unroll
        for (int cc = 0; cc < C_; cc++){
            const float* tr = &T_sh[cc][0];
            float best = hv[0] + tr[0];
            int idx = 0;
#pragma unroll
            for (int j = 1; j < C_; j++){
                float val = hv[j] + tr[j];
                bool gt = val > best;          // strict > : leftmost wins ties
                best = gt ? val : best;
                idx  = gt ? j : idx;
            }
            bp_sh[t][cc] = (signed char)idx;
        }
    }

    // final score + start tag (warp 0)
    float fv = -3.4e38f; int fi = 999;
    if (tid < 32){
        int lane = tid;
        bool active = lane < C_;
        if (active)
            fv = g_hist[((size_t)b * (L_ + 1) + L_) * CP + lane]
               + trans[(C_ - 1) * C_ + lane];
        if (active) fi = lane;
#pragma unroll
        for (int off = 16; off > 0; off >>= 1){
            float ov = __shfl_down_sync(0xffffffffu, fv, off);
            int oi = __shfl_down_sync(0xffffffffu, fi, off);
            if (ov > fv || (ov == fv && oi < fi)){ fv = ov; fi = oi; }
        }
    }
    __syncthreads();

    if (tid == 0){
        out[b] = fv;
        int cur = fi;
        for (int t = L_ - 1; t >= 0; t--){
            bool valid = m2[t] > 0.f;
            bp_sh[t][C_] = valid ? (signed char)cur : (signed char)(-1);
            if (valid) cur = bp_sh[t][cur];
        }
    }
    __syncthreads();

    float* po = out + B_ + (size_t)b * L_;
    po[tid] = (float)bp_sh[tid][C_];
}

// ---------------------------------------------------------------------------
extern "C" void kernel_launch(void* const* d_in, const int* in_sizes, int n_in,
                              void* d_out, int out_size){
    const float* feats = (const float*)d_in[0];
    const float* masks = (const float*)d_in[1];
    const float* W     = (const float*)d_in[2];
    const float* bias  = (const float*)d_in[3];
    const float* trans = (const float*)d_in[4];
    float* out = (float*)d_out;

    cudaFuncSetAttribute(emis_kernel, cudaFuncAttributeMaxDynamicSharedMemorySize, SMEM_A);
    emis_kernel<<<256, 256, SMEM_A>>>(feats, W, bias);
    fwd_kernel<<<B_, 32>>>(masks, trans);
    bp_kernel<<<B_, 512>>>(masks, trans, out);
}

// round 8
// speedup vs baseline: 1.3063x; 1.2185x over previous
#include <cuda_runtime.h>
#include <cstdint>
#include <cstddef>

#define B_ 256
#define L_ 512
#define D_ 768
#define C_ 19
#define CP 20
#define BL (B_*L_)

// Emission scratch, padded to 20 floats/row
__device__ float g_emis[(size_t)BL * CP];
// Score history: rows 0..512 per batch (row 0 = init, row t+1 = s after step t)
__device__ float g_hist[(size_t)B_ * (L_ + 1) * CP];

__device__ __forceinline__ unsigned long long pack2(float x){
    unsigned long long r;
    asm("mov.b64 %0, {%1, %1};" : "=l"(r) : "f"(x));
    return r;
}
__device__ __forceinline__ unsigned long long fma2(unsigned long long a,
                                                   unsigned long long b,
                                                   unsigned long long c){
    unsigned long long d;
    asm("fma.rn.f32x2 %0, %1, %2, %3;" : "=l"(d) : "l"(a), "l"(b), "l"(c));
    return d;
}

#define SMEM_A (D_ * 10 * 8)   // 61440 bytes: w2[d][p] packed class pairs

// ---------------------------------------------------------------------------
// Kernel A: emissions — EXACT R2 configuration (best measured: 151us).
// 256 blocks x 256 threads, 2 rows/thread, LDS.64 weight broadcast,
// packed f32x2 FMA. No launch_bounds minimum, no prefetch ring.
// ---------------------------------------------------------------------------
__global__ void __launch_bounds__(256) emis_kernel(const float* __restrict__ feats,
                                                   const float* __restrict__ W,
                                                   const float* __restrict__ bias){
    extern __shared__ unsigned long long w2[];   // [768*10]
    int tid = threadIdx.x;
    for (int i = tid; i < D_ * 10; i += 256){
        int d = i / 10, p = i % 10;
        float lo = W[(2*p) * D_ + d];
        float hi = (2*p + 1 < C_) ? W[(2*p + 1) * D_ + d] : 0.f;
        float2 t = make_float2(lo, hi);
        w2[i] = *reinterpret_cast<unsigned long long*>(&t);
    }
    __syncthreads();

    unsigned long long accA[10], accB[10];
#pragma unroll
    for (int p = 0; p < 10; p++){
        float lo = bias[2*p];
        float hi = (2*p + 1 < C_) ? bias[2*p + 1] : 0.f;
        float2 t = make_float2(lo, hi);
        accA[p] = *reinterpret_cast<unsigned long long*>(&t);
        accB[p] = accA[p];
    }

    size_t rowA = (size_t)blockIdx.x * 512 + tid;
    size_t rowB = rowA + 256;
    const float4* fA = reinterpret_cast<const float4*>(feats + rowA * D_);
    const float4* fB = reinterpret_cast<const float4*>(feats + rowB * D_);

    for (int q = 0; q < D_ / 4; q++){
        float4 a = fA[q], b = fB[q];
#pragma unroll
        for (int j = 0; j < 4; j++){
            float av = (&a.x)[j], bv = (&b.x)[j];
            unsigned long long pa = pack2(av), pb = pack2(bv);
            int d = q * 4 + j;
#pragma unroll
            for (int p = 0; p < 10; p++){
                unsigned long long w = w2[d * 10 + p];
                accA[p] = fma2(pa, w, accA[p]);
                accB[p] = fma2(pb, w, accB[p]);
            }
        }
    }

    unsigned long long* oA = reinterpret_cast<unsigned long long*>(g_emis + rowA * CP);
    unsigned long long* oB = reinterpret_cast<unsigned long long*>(g_emis + rowB * CP);
#pragma unroll
    for (int p = 0; p < 10; p++){ oA[p] = accA[p]; oB[p] = accB[p]; }
}

// ---------------------------------------------------------------------------
// Kernel B1: Viterbi forward, syncless smem gather. One warp per batch,
// 256 blocks x 32 threads. The warp never diverges, so the warp-wide
// STS -> LDS pair flows in order through the one LSU queue: no __syncwarp
// on the chain, single staging buffer. All 32 lanes store (row padded to
// 32 floats), only floats 0..18 are consumed. History streamed to gmem
// (off-path STG) for the bp kernel.
// ---------------------------------------------------------------------------
__global__ void __launch_bounds__(32) fwd_kernel(const float* __restrict__ masks,
                                                 const float* __restrict__ trans){
    __shared__ float m_sh[L_];
    __shared__ float stage[32];
    int lane = threadIdx.x & 31;
    int b = blockIdx.x;
    bool active = lane < C_;
    int c = active ? lane : 0;

    float Trow[C_];
#pragma unroll
    for (int j = 0; j < C_; j++) Trow[j] = trans[c * C_ + j];

    const float* eb = g_emis + (size_t)b * L_ * CP;
    const float* mb = masks + (size_t)b * L_;
    float* ghb = g_hist + (size_t)b * (L_ + 1) * CP;

    for (int i = lane; i < L_; i += 32) m_sh[i] = mb[i];
    __syncwarp();

    float s = (lane == C_ - 2) ? 0.f : -10000.f;   // start_idx = C-2
    if (active) ghb[lane] = s;

    int ld_lane = active ? lane : 0;
    float e0 = eb[0 * CP + ld_lane];
    float e1 = eb[1 * CP + ld_lane];
    float e2 = eb[2 * CP + ld_lane];
    float e3 = eb[3 * CP + ld_lane];

#define VSTEP(T, EREG)                                                         \
    {                                                                          \
        float m = m_sh[T];                                                     \
        float om = 1.0f - m;                                                   \
        float inner = fmaf((EREG), m, s * om);   /* off critical path */       \
        stage[lane] = s;                          /* warp-wide STS */          \
        float4 g0 = *reinterpret_cast<const float4*>(&stage[0]);               \
        float4 g1 = *reinterpret_cast<const float4*>(&stage[4]);               \
        float4 g2 = *reinterpret_cast<const float4*>(&stage[8]);               \
        float4 g3 = *reinterpret_cast<const float4*>(&stage[12]);              \
        float4 g4 = *reinterpret_cast<const float4*>(&stage[16]);              \
        float v[C_];                                                           \
        v[0]=g0.x+Trow[0];  v[1]=g0.y+Trow[1];  v[2]=g0.z+Trow[2];             \
        v[3]=g0.w+Trow[3];  v[4]=g1.x+Trow[4];  v[5]=g1.y+Trow[5];             \
        v[6]=g1.z+Trow[6];  v[7]=g1.w+Trow[7];  v[8]=g2.x+Trow[8];             \
        v[9]=g2.y+Trow[9];  v[10]=g2.z+Trow[10]; v[11]=g2.w+Trow[11];          \
        v[12]=g3.x+Trow[12]; v[13]=g3.y+Trow[13]; v[14]=g3.z+Trow[14];         \
        v[15]=g3.w+Trow[15]; v[16]=g4.x+Trow[16]; v[17]=g4.y+Trow[17];         \
        v[18]=g4.z+Trow[18];                                                   \
        _Pragma("unroll")                                                      \
        for (int stp = 1; stp < C_; stp <<= 1){                                \
            _Pragma("unroll")                                                  \
            for (int j = 0; j + stp < C_; j += (stp << 1))                     \
                v[j] = fmaxf(v[j], v[j + stp]);                                \
        }                                                                      \
        s = fmaf(v[0], m, inner);                                              \
        if (active) ghb[((T) + 1) * CP + lane] = s;                            \
    }

    for (int t = 0; t < L_; t += 4){
        VSTEP(t, e0);     e0 = (t + 4 < L_) ? eb[(t + 4) * CP + ld_lane] : 0.f;
        VSTEP(t + 1, e1); e1 = (t + 5 < L_) ? eb[(t + 5) * CP + ld_lane] : 0.f;
        VSTEP(t + 2, e2); e2 = (t + 6 < L_) ? eb[(t + 6) * CP + ld_lane] : 0.f;
        VSTEP(t + 3, e3); e3 = (t + 7 < L_) ? eb[(t + 7) * CP + ld_lane] : 0.f;
    }
#undef VSTEP
}

// ---------------------------------------------------------------------------
// Kernel B2: backpointers + backtrace. One block per batch, one thread per
// timestep recomputes all 19 backpointers from the score history; thread 0
// backtraces from shared; coalesced tag writeback.
// ---------------------------------------------------------------------------
__global__ void __launch_bounds__(512) bp_kernel(const float* __restrict__ masks,
                                                 const float* __restrict__ trans,
                                                 float* __restrict__ out){
    __shared__ float T_sh[C_][CP];
    __shared__ float m2[L_];
    __shared__ signed char bp_sh[L_][CP];   // col 19 reused for tags
    int tid = threadIdx.x;
    int b = blockIdx.x;

    for (int i = tid; i < C_ * CP; i += 512){
        int cc = i / CP, j = i % CP;
        T_sh[cc][j] = (j < C_) ? trans[cc * C_ + j] : 0.f;
    }
    if (tid < L_) m2[tid] = masks[(size_t)b * L_ + tid];
    __syncthreads();

    {
        int t = tid;   // 0..511
        const float* h = g_hist + ((size_t)b * (L_ + 1) + t) * CP;
        float4 h0 = *reinterpret_cast<const float4*>(h + 0);
        float4 h1 = *reinterpret_cast<const float4*>(h + 4);
        float4 h2 = *reinterpret_cast<const float4*>(h + 8);
        float4 h3 = *reinterpret_cast<const float4*>(h + 12);
        float4 h4 = *reinterpret_cast<const float4*>(h + 16);
        float hv[C_];
        hv[0]=h0.x; hv[1]=h0.y; hv[2]=h0.z; hv[3]=h0.w;
        hv[4]=h1.x; hv[5]=h1.y; hv[6]=h1.z; hv[7]=h1.w;
        hv[8]=h2.x; hv[9]=h2.y; hv[10]=h2.z; hv[11]=h2.w;
        hv[12]=h3.x; hv[13]=h3.y; hv[14]=h3.z; hv[15]=h3.w;
        hv[16]=h4.x; hv[17]=h4.y; hv[18]=h4.z;

#pragma unroll
        for (int cc = 0; cc < C_; cc++){
            const float* tr = &T_sh[cc][0];
            float best = hv[0] + tr[0];
            int idx = 0;
#pragma unroll
            for (int j = 1; j < C_; j++){
                float val = hv[j] + tr[j];
                bool gt = val > best;          // strict > : leftmost wins ties
                best = gt ? val : best;
                idx  = gt ? j : idx;
            }
            bp_sh[t][cc] = (signed char)idx;
        }
    }

    // final score + start tag (warp 0)
    float fv = -3.4e38f; int fi = 999;
    if (tid < 32){
        int lane = tid;
        bool active = lane < C_;
        if (active)
            fv = g_hist[((size_t)b * (L_ + 1) + L_) * CP + lane]
               + trans[(C_ - 1) * C_ + lane];
        if (active) fi = lane;
#pragma unroll
        for (int off = 16; off > 0; off >>= 1){
            float ov = __shfl_down_sync(0xffffffffu, fv, off);
            int oi = __shfl_down_sync(0xffffffffu, fi, off);
            if (ov > fv || (ov == fv && oi < fi)){ fv = ov; fi = oi; }
        }
    }
    __syncthreads();

    if (tid == 0){
        out[b] = fv;
        int cur = fi;
        for (int t = L_ - 1; t >= 0; t--){
            bool valid = m2[t] > 0.f;
            bp_sh[t][C_] = valid ? (signed char)cur : (signed char)(-1);
            if (valid) cur = bp_sh[t][cur];
        }
    }
    __syncthreads();

    float* po = out + B_ + (size_t)b * L_;
    po[tid] = (float)bp_sh[tid][C_];
}

// ---------------------------------------------------------------------------
extern "C" void kernel_launch(void* const* d_in, const int* in_sizes, int n_in,
                              void* d_out, int out_size){
    const float* feats = (const float*)d_in[0];
    const float* masks = (const float*)d_in[1];
    const float* W     = (const float*)d_in[2];
    const float* bias  = (const float*)d_in[3];
    const float* trans = (const float*)d_in[4];
    float* out = (float*)d_out;

    cudaFuncSetAttribute(emis_kernel, cudaFuncAttributeMaxDynamicSharedMemorySize, SMEM_A);
    emis_kernel<<<256, 256, SMEM_A>>>(feats, W, bias);
    fwd_kernel<<<B_, 32>>>(masks, trans);
    bp_kernel<<<B_, 512>>>(masks, trans, out);
}